// round 1
// baseline (speedup 1.0000x reference)
#include <cuda_runtime.h>
#include <cuda_bf16.h>

// Output: pos[b=32, F=512, h=64, w=64] fp32.
// pos[b][f][i][j] = row_embed[Z(i,j)][f],  Z = max(|32-j| + |32-i| - 1, 0) in [0,63].
// Pure store-bound: 256 MiB writes, 128 KB effective reads.

static constexpr int NUM_POS_FEATS = 512;  // F
static constexpr int LEN_EMB       = 64;   // rows of row_embed (Z range)
static constexpr int H = 64, W = 64;
static constexpr int BATCH = 32;

__global__ __launch_bounds__(256, 8)
void pe_kernel(const float* __restrict__ row_embed, float* __restrict__ out) {
    __shared__ float s[LEN_EMB];

    const int f = blockIdx.x;   // 0..511
    const int b = blockIdx.y;   // 0..31
    const int tid = threadIdx.x;

    // Stage column f of row_embed: s[z] = row_embed[z*512 + f]
    if (tid < LEN_EMB) {
        s[tid] = row_embed[tid * NUM_POS_FEATS + f];
    }
    __syncthreads();

    // This block owns one 64x64 plane = 4096 floats = 1024 float4.
    float4* o = reinterpret_cast<float4*>(
        out + ((size_t)(b * NUM_POS_FEATS + f)) * (H * W));

    #pragma unroll
    for (int k = 0; k < 4; k++) {
        const int p  = tid + k * 256;      // float4 index 0..1023
        const int i  = p >> 4;             // row 0..63
        const int j0 = (p & 15) << 2;      // col 0,4,...,60
        const int di = abs(32 - i) - 1;    // fold -1 into the row term

        float4 v;
        v.x = s[max(di + abs(32 - (j0 + 0)), 0)];
        v.y = s[max(di + abs(32 - (j0 + 1)), 0)];
        v.z = s[max(di + abs(32 - (j0 + 2)), 0)];
        v.w = s[max(di + abs(32 - (j0 + 3)), 0)];
        o[p] = v;
    }
}

extern "C" void kernel_launch(void* const* d_in, const int* in_sizes, int n_in,
                              void* d_out, int out_size) {
    // d_in[0] = x (shape-only, unused), d_in[1] = row_embed [64, 512] fp32
    const float* row_embed = (const float*)d_in[1];
    float* out = (float*)d_out;

    dim3 grid(NUM_POS_FEATS, BATCH);  // (512, 32)
    pe_kernel<<<grid, 256>>>(row_embed, out);
}